// round 8
// baseline (speedup 1.0000x reference)
#include <cuda_runtime.h>

#define DI __device__ __forceinline__

constexpr int Bn = 2, Sn = 2048, Dn = 1024, Hn = 16, DEPn = 64, BHn = 32, Mn = 4096;
constexpr long long OUT_ELEMS = (long long)Mn * Dn;

__device__ float g_Qh[(size_t)BHn * Sn * DEPn];
__device__ float g_Kh[(size_t)BHn * Sn * DEPn];
__device__ float g_Vh[(size_t)BHn * Sn * DEPn];
__device__ float g_Oh[(size_t)Mn * Dn];

DI unsigned f2tf(float f) {
    unsigned u;
    asm("cvt.rna.tf32.f32 %0, %1;" : "=r"(u) : "f"(f));
    return u;
}

DI void mma8(float* c, unsigned a0, unsigned a1, unsigned a2, unsigned a3,
             unsigned b0, unsigned b1) {
    asm volatile(
        "mma.sync.aligned.m16n8k8.row.col.f32.tf32.tf32.f32 "
        "{%0,%1,%2,%3}, {%4,%5,%6,%7}, {%8,%9}, {%0,%1,%2,%3};\n"
        : "+f"(c[0]), "+f"(c[1]), "+f"(c[2]), "+f"(c[3])
        : "r"(a0), "r"(a1), "r"(a2), "r"(a3), "r"(b0), "r"(b1));
}

// split x into hi(tf32) + lo(tf32 of residual)
DI void split_tf(float x, unsigned& hi, unsigned& lo) {
    hi = f2tf(x);
    lo = f2tf(x - __uint_as_float(hi));
}

// ---------------------------------------------------------------------------
// Projection GEMM: C[4096,N=1024] = A @ W + bias, 3xTF32, optional head-split.
// ---------------------------------------------------------------------------
struct ProjParams {
    const float* A[3];
    const float* W[3];
    const float* bias[3];
    float*       out[3];
    float        scale[3];
    int          headsplit;
};

constexpr int PAS = 36, PBS = 136;
constexpr int PROJ_SMEM = (2 * 128 * PAS + 2 * 32 * PBS) * 4;

__global__ __launch_bounds__(256) void proj_gemm(ProjParams pp) {
    extern __shared__ unsigned psm[];
    unsigned* Ah = psm;
    unsigned* Al = Ah + 128 * PAS;
    unsigned* Bh = Al + 128 * PAS;
    unsigned* Bl = Bh + 32 * PBS;

    const int z = blockIdx.z;
    const float* __restrict__ A    = pp.A[z];
    const float* __restrict__ W    = pp.W[z];
    const float* __restrict__ bias = pp.bias[z];
    float* __restrict__ out        = pp.out[z];
    const float oscale             = pp.scale[z];

    const int tid = threadIdx.x, warp = tid >> 5, lane = tid & 31;
    const int gid = lane >> 2, tig = lane & 3;
    const int wm = (warp >> 2) * 64, wn = (warp & 3) * 32;
    const int bm0 = blockIdx.y * 128, bn0 = blockIdx.x * 128;
    const int ar = tid >> 1, akq = (tid & 1) * 16;
    const int bk = tid >> 3, bnq = (tid & 7) * 16;

    float c[4][4][4];
#pragma unroll
    for (int mi = 0; mi < 4; ++mi)
#pragma unroll
        for (int ni = 0; ni < 4; ++ni)
#pragma unroll
            for (int e = 0; e < 4; ++e) c[mi][ni][e] = 0.f;

    for (int kt = 0; kt < Dn / 32; ++kt) {
        const int k0 = kt * 32;
        {
            const float4* ag = reinterpret_cast<const float4*>(
                A + (size_t)(bm0 + ar) * Dn + k0 + akq);
#pragma unroll
            for (int u = 0; u < 4; ++u) {
                float4 v = ag[u];
                unsigned* dh = &Ah[ar * PAS + akq + u * 4];
                unsigned* dl = &Al[ar * PAS + akq + u * 4];
                split_tf(v.x, dh[0], dl[0]); split_tf(v.y, dh[1], dl[1]);
                split_tf(v.z, dh[2], dl[2]); split_tf(v.w, dh[3], dl[3]);
            }
            const float4* bg = reinterpret_cast<const float4*>(
                W + (size_t)(k0 + bk) * Dn + bn0 + bnq);
#pragma unroll
            for (int u = 0; u < 4; ++u) {
                float4 v = bg[u];
                unsigned* dh = &Bh[bk * PBS + bnq + u * 4];
                unsigned* dl = &Bl[bk * PBS + bnq + u * 4];
                split_tf(v.x, dh[0], dl[0]); split_tf(v.y, dh[1], dl[1]);
                split_tf(v.z, dh[2], dl[2]); split_tf(v.w, dh[3], dl[3]);
            }
        }
        __syncthreads();
#pragma unroll
        for (int ks = 0; ks < 4; ++ks) {
            unsigned ah[4][4], al[4][4];
#pragma unroll
            for (int mi = 0; mi < 4; ++mi) {
                const int r = wm + mi * 16 + gid;
                const int kc = ks * 8 + tig;
                ah[mi][0] = Ah[r * PAS + kc];       ah[mi][1] = Ah[(r + 8) * PAS + kc];
                ah[mi][2] = Ah[r * PAS + kc + 4];   ah[mi][3] = Ah[(r + 8) * PAS + kc + 4];
                al[mi][0] = Al[r * PAS + kc];       al[mi][1] = Al[(r + 8) * PAS + kc];
                al[mi][2] = Al[r * PAS + kc + 4];   al[mi][3] = Al[(r + 8) * PAS + kc + 4];
            }
#pragma unroll
            for (int ni = 0; ni < 4; ++ni) {
                const int bc = wn + ni * 8 + gid;
                const unsigned b0h = Bh[(ks * 8 + tig) * PBS + bc];
                const unsigned b1h = Bh[(ks * 8 + tig + 4) * PBS + bc];
                const unsigned b0l = Bl[(ks * 8 + tig) * PBS + bc];
                const unsigned b1l = Bl[(ks * 8 + tig + 4) * PBS + bc];
#pragma unroll
                for (int mi = 0; mi < 4; ++mi) {
                    mma8(c[mi][ni], ah[mi][0], ah[mi][1], ah[mi][2], ah[mi][3], b0h, b1h);
                    mma8(c[mi][ni], ah[mi][0], ah[mi][1], ah[mi][2], ah[mi][3], b0l, b1l);
                    mma8(c[mi][ni], al[mi][0], al[mi][1], al[mi][2], al[mi][3], b0h, b1h);
                }
            }
        }
        __syncthreads();
    }

#pragma unroll
    for (int mi = 0; mi < 4; ++mi)
#pragma unroll
        for (int ni = 0; ni < 4; ++ni)
#pragma unroll
            for (int hh = 0; hh < 2; ++hh) {
                const int row = bm0 + wm + mi * 16 + gid + hh * 8;
                const int col = bn0 + wn + ni * 8 + tig * 2;
                float2 v;
                v.x = (c[mi][ni][hh * 2 + 0] + bias[col])     * oscale;
                v.y = (c[mi][ni][hh * 2 + 1] + bias[col + 1]) * oscale;
                size_t idx;
                if (pp.headsplit) {
                    const int b = row >> 11, s = row & (Sn - 1);
                    const int h = col >> 6, d = col & 63;
                    idx = (((size_t)(b * Hn + h)) * Sn + s) * DEPn + d;
                } else {
                    idx = (size_t)row * Dn + col;
                }
                *reinterpret_cast<float2*>(out + idx) = v;
            }
}

// ---------------------------------------------------------------------------
// Scores: S[bh, mt*128.., nt*128..] = Qh @ Kh^T + penalty  (3xTF32)
// ---------------------------------------------------------------------------
constexpr int QST = 68;
constexpr int SC_SMEM = (4 * 128 * QST) * 4 + 512;

__global__ __launch_bounds__(256) void scores_kernel(const float* __restrict__ mask,
                                                     float* __restrict__ attn) {
    extern __shared__ unsigned ssm[];
    unsigned* Qh = ssm;
    unsigned* Ql = Qh + 128 * QST;
    unsigned* Kh = Ql + 128 * QST;
    unsigned* Kl = Kh + 128 * QST;
    float* Msk = reinterpret_cast<float*>(Kl + 128 * QST);

    const int nt = blockIdx.x, mt = blockIdx.y, bh = blockIdx.z;
    const int b = bh >> 4;
    const int tid = threadIdx.x, warp = tid >> 5, lane = tid & 31;
    const int gid = lane >> 2, tig = lane & 3;
    const int wrow = warp * 16;
    float* Sout = attn + ((size_t)bh * Sn + mt * 128) * Sn + nt * 128;

    if (nt > mt) {  // fully masked tile: constant fill
        const int lr = tid >> 1, cq = (tid & 1) * 64;
        const float4 z4 = make_float4(-1e17f, -1e17f, -1e17f, -1e17f);
        float4* dst = reinterpret_cast<float4*>(Sout + (size_t)lr * Sn + cq);
#pragma unroll
        for (int u = 0; u < 16; ++u) dst[u] = z4;
        return;
    }

    {
        const int lr = tid >> 1, lq = (tid & 1) * 32;
        const float4* qg = reinterpret_cast<const float4*>(
            g_Qh + ((size_t)bh * Sn + mt * 128 + lr) * DEPn + lq);
        const float4* kg = reinterpret_cast<const float4*>(
            g_Kh + ((size_t)bh * Sn + nt * 128 + lr) * DEPn + lq);
#pragma unroll
        for (int u = 0; u < 8; ++u) {
            float4 v = qg[u];
            unsigned* dh = &Qh[lr * QST + lq + u * 4];
            unsigned* dl = &Ql[lr * QST + lq + u * 4];
            split_tf(v.x, dh[0], dl[0]); split_tf(v.y, dh[1], dl[1]);
            split_tf(v.z, dh[2], dl[2]); split_tf(v.w, dh[3], dl[3]);
            float4 w = kg[u];
            unsigned* eh = &Kh[lr * QST + lq + u * 4];
            unsigned* el = &Kl[lr * QST + lq + u * 4];
            split_tf(w.x, eh[0], el[0]); split_tf(w.y, eh[1], el[1]);
            split_tf(w.z, eh[2], el[2]); split_tf(w.w, eh[3], el[3]);
        }
        if (tid < 128) Msk[tid] = mask[(size_t)b * Sn + nt * 128 + tid];
    }
    __syncthreads();

    float c[16][4];
#pragma unroll
    for (int nf = 0; nf < 16; ++nf) { c[nf][0] = c[nf][1] = c[nf][2] = c[nf][3] = 0.f; }

#pragma unroll
    for (int ks = 0; ks < 8; ++ks) {
        const int kc = ks * 8 + tig;
        const unsigned a0h = Qh[(wrow + gid) * QST + kc];
        const unsigned a1h = Qh[(wrow + gid + 8) * QST + kc];
        const unsigned a2h = Qh[(wrow + gid) * QST + kc + 4];
        const unsigned a3h = Qh[(wrow + gid + 8) * QST + kc + 4];
        const unsigned a0l = Ql[(wrow + gid) * QST + kc];
        const unsigned a1l = Ql[(wrow + gid + 8) * QST + kc];
        const unsigned a2l = Ql[(wrow + gid) * QST + kc + 4];
        const unsigned a3l = Ql[(wrow + gid + 8) * QST + kc + 4];
#pragma unroll
        for (int nf = 0; nf < 16; ++nf) {
            const unsigned b0h = Kh[(nf * 8 + gid) * QST + kc];
            const unsigned b1h = Kh[(nf * 8 + gid) * QST + kc + 4];
            const unsigned b0l = Kl[(nf * 8 + gid) * QST + kc];
            const unsigned b1l = Kl[(nf * 8 + gid) * QST + kc + 4];
            mma8(c[nf], a0h, a1h, a2h, a3h, b0h, b1h);
            mma8(c[nf], a0h, a1h, a2h, a3h, b0l, b1l);
            mma8(c[nf], a0l, a1l, a2l, a3l, b0h, b1h);
        }
    }

    const int grow0 = mt * 128 + wrow + gid;
#pragma unroll
    for (int nf = 0; nf < 16; ++nf)
#pragma unroll
        for (int hh = 0; hh < 2; ++hh) {
            float2 v;
#pragma unroll
            for (int e = 0; e < 2; ++e) {
                const int cl = nf * 8 + tig * 2 + e;
                const int gcol = nt * 128 + cl;
                const float pen =
                    fmaxf(Msk[cl], (gcol > grow0 + hh * 8) ? 1.0f : 0.0f) * -1e17f;
                (&v.x)[e] = c[nf][hh * 2 + e] + pen;
            }
            *reinterpret_cast<float2*>(
                Sout + (size_t)(wrow + gid + hh * 8) * Sn + nf * 8 + tig * 2) = v;
        }
}

// ---------------------------------------------------------------------------
// Softmax: one CTA per row of the (BH*S, S) score matrix, in place.
// ---------------------------------------------------------------------------
__global__ __launch_bounds__(256) void softmax_rows(float* __restrict__ attn) {
    __shared__ float red[8];
    float* p = attn + (size_t)blockIdx.x * Sn;
    const int tid = threadIdx.x, lane = tid & 31, wid = tid >> 5;

    float4 v0 = reinterpret_cast<const float4*>(p)[tid];
    float4 v1 = reinterpret_cast<const float4*>(p)[256 + tid];
    float m = fmaxf(fmaxf(fmaxf(v0.x, v0.y), fmaxf(v0.z, v0.w)),
                    fmaxf(fmaxf(v1.x, v1.y), fmaxf(v1.z, v1.w)));
#pragma unroll
    for (int o = 16; o; o >>= 1) m = fmaxf(m, __shfl_xor_sync(~0u, m, o));
    if (lane == 0) red[wid] = m;
    __syncthreads();
    m = red[0];
#pragma unroll
    for (int i = 1; i < 8; ++i) m = fmaxf(m, red[i]);
    __syncthreads();

    float4 e0, e1;
    e0.x = __expf(v0.x - m); e0.y = __expf(v0.y - m);
    e0.z = __expf(v0.z - m); e0.w = __expf(v0.w - m);
    e1.x = __expf(v1.x - m); e1.y = __expf(v1.y - m);
    e1.z = __expf(v1.z - m); e1.w = __expf(v1.w - m);
    float s = e0.x + e0.y + e0.z + e0.w + e1.x + e1.y + e1.z + e1.w;
#pragma unroll
    for (int o = 16; o; o >>= 1) s += __shfl_xor_sync(~0u, s, o);
    if (lane == 0) red[wid] = s;
    __syncthreads();
    s = red[0] + red[1] + red[2] + red[3] + red[4] + red[5] + red[6] + red[7];
    const float inv = 1.0f / s;

    e0.x *= inv; e0.y *= inv; e0.z *= inv; e0.w *= inv;
    e1.x *= inv; e1.y *= inv; e1.z *= inv; e1.w *= inv;
    reinterpret_cast<float4*>(p)[tid] = e0;
    reinterpret_cast<float4*>(p)[256 + tid] = e1;
}

// ---------------------------------------------------------------------------
// O = P @ V per (mtile, bh); plain tf32. Causal chunks only (P==0 above diag).
// ---------------------------------------------------------------------------
constexpr int PST = 132, VTS = 132;
constexpr int PV_SMEM = (128 * PST + 64 * VTS) * 4;

__global__ __launch_bounds__(256) void pv_kernel(const float* __restrict__ attn) {
    extern __shared__ unsigned vsm[];
    unsigned* Ps = vsm;
    unsigned* Vt = Ps + 128 * PST;

    const int mt = blockIdx.x, bh = blockIdx.y;
    const int b = bh >> 4, h = bh & 15;
    const int tid = threadIdx.x, warp = tid >> 5, lane = tid & 31;
    const int gid = lane >> 2, tig = lane & 3;
    const int wrow = warp * 16;

    const float* Pg = attn + ((size_t)bh * Sn + mt * 128) * Sn;
    const float* Vg = g_Vh + (size_t)bh * Sn * DEPn;

    float c[8][4];
#pragma unroll
    for (int nf = 0; nf < 8; ++nf) { c[nf][0] = c[nf][1] = c[nf][2] = c[nf][3] = 0.f; }

    for (int j = 0; j <= mt; ++j) {
        __syncthreads();
        {
            const int lr = tid >> 1, lq = (tid & 1) * 64;
            const float4* pg = reinterpret_cast<const float4*>(
                Pg + (size_t)lr * Sn + j * 128 + lq);
#pragma unroll
            for (int u = 0; u < 16; ++u) {
                float4 v = pg[u];
                unsigned* d = &Ps[lr * PST + lq + u * 4];
                d[0] = f2tf(v.x); d[1] = f2tf(v.y); d[2] = f2tf(v.z); d[3] = f2tf(v.w);
            }
            const int lv = tid >> 1, cq = (tid & 1) * 32;
            const float4* vg = reinterpret_cast<const float4*>(
                Vg + (size_t)(j * 128 + lv) * DEPn + cq);
#pragma unroll
            for (int u = 0; u < 8; ++u) {
                float4 v = vg[u];
                Vt[(cq + u * 4 + 0) * VTS + lv] = f2tf(v.x);
                Vt[(cq + u * 4 + 1) * VTS + lv] = f2tf(v.y);
                Vt[(cq + u * 4 + 2) * VTS + lv] = f2tf(v.z);
                Vt[(cq + u * 4 + 3) * VTS + lv] = f2tf(v.w);
            }
        }
        __syncthreads();
#pragma unroll
        for (int ks = 0; ks < 16; ++ks) {
            const int kc = ks * 8 + tig;
            const unsigned a0 = Ps[(wrow + gid) * PST + kc];
            const unsigned a1 = Ps[(wrow + gid + 8) * PST + kc];
            const unsigned a2 = Ps[(wrow + gid) * PST + kc + 4];
            const unsigned a3 = Ps[(wrow + gid + 8) * PST + kc + 4];
#pragma unroll
            for (int nf = 0; nf < 8; ++nf) {
                const unsigned b0 = Vt[(nf * 8 + gid) * VTS + kc];
                const unsigned b1 = Vt[(nf * 8 + gid) * VTS + kc + 4];
                mma8(c[nf], a0, a1, a2, a3, b0, b1);
            }
        }
    }

#pragma unroll
    for (int nf = 0; nf < 8; ++nf)
#pragma unroll
        for (int hh = 0; hh < 2; ++hh) {
            const int s = mt * 128 + wrow + gid + hh * 8;
            const int col = nf * 8 + tig * 2;
            float2 v;
            v.x = c[nf][hh * 2 + 0];
            v.y = c[nf][hh * 2 + 1];
            *reinterpret_cast<float2*>(
                g_Oh + ((size_t)(b * Sn + s)) * Dn + h * 64 + col) = v;
        }
}

// ---------------------------------------------------------------------------
extern "C" void kernel_launch(void* const* d_in, const int* in_sizes, int n_in,
                              void* d_out, int out_size) {
    const float* v    = (const float*)d_in[0];
    const float* k    = (const float*)d_in[1];
    const float* q    = (const float*)d_in[2];
    const float* mask = (const float*)d_in[3];
    const float* Wq = (const float*)d_in[4],  *bq = (const float*)d_in[5];
    const float* Wk = (const float*)d_in[6],  *bk = (const float*)d_in[7];
    const float* Wv = (const float*)d_in[8],  *bv = (const float*)d_in[9];
    const float* Wo = (const float*)d_in[10], *bo = (const float*)d_in[11];

    float* out  = (float*)d_out;
    float* attn = out + OUT_ELEMS;

    void *pQ, *pK, *pV, *pO;
    cudaGetSymbolAddress(&pQ, g_Qh);
    cudaGetSymbolAddress(&pK, g_Kh);
    cudaGetSymbolAddress(&pV, g_Vh);
    cudaGetSymbolAddress(&pO, g_Oh);

    cudaFuncSetAttribute(proj_gemm, cudaFuncAttributeMaxDynamicSharedMemorySize, PROJ_SMEM);
    cudaFuncSetAttribute(scores_kernel, cudaFuncAttributeMaxDynamicSharedMemorySize, SC_SMEM);
    cudaFuncSetAttribute(pv_kernel, cudaFuncAttributeMaxDynamicSharedMemorySize, PV_SMEM);

    ProjParams p1;
    p1.A[0] = q;  p1.W[0] = Wq; p1.bias[0] = bq; p1.out[0] = (float*)pQ; p1.scale[0] = 0.125f;
    p1.A[1] = k;  p1.W[1] = Wk; p1.bias[1] = bk; p1.out[1] = (float*)pK; p1.scale[1] = 1.0f;
    p1.A[2] = v;  p1.W[2] = Wv; p1.bias[2] = bv; p1.out[2] = (float*)pV; p1.scale[2] = 1.0f;
    p1.headsplit = 1;
    proj_gemm<<<dim3(8, 32, 3), 256, PROJ_SMEM>>>(p1);

    scores_kernel<<<dim3(16, 16, 32), 256, SC_SMEM>>>(mask, attn);
    softmax_rows<<<BHn * Sn, 256>>>(attn);
    pv_kernel<<<dim3(16, 32), 256, PV_SMEM>>>(attn);

    ProjParams p2;
    p2.A[0] = (const float*)pO; p2.W[0] = Wo; p2.bias[0] = bo;
    p2.out[0] = out; p2.scale[0] = 1.0f;
    p2.A[1] = p2.A[0]; p2.W[1] = p2.W[0]; p2.bias[1] = p2.bias[0];
    p2.out[1] = p2.out[0]; p2.scale[1] = 1.0f;
    p2.A[2] = p2.A[0]; p2.W[2] = p2.W[0]; p2.bias[2] = p2.bias[0];
    p2.out[2] = p2.out[0]; p2.scale[2] = 1.0f;
    p2.headsplit = 0;
    proj_gemm<<<dim3(8, 32, 1), 256, PROJ_SMEM>>>(p2);
}

// round 9
// speedup vs baseline: 2.0886x; 2.0886x over previous
#include <cuda_runtime.h>
#include <cuda_bf16.h>

#define DI __device__ __forceinline__

constexpr int Bn = 2, Sn = 2048, Dn = 1024, Hn = 16, DEPn = 64, BHn = 32, Mn = 4096;
constexpr long long OUT_ELEMS = (long long)Mn * Dn;
constexpr size_t AW = (size_t)Mn * 512;   // activation words per half-matrix
constexpr size_t WW = (size_t)Dn * 512;   // weight words per half-matrix

// scratch (__device__ globals: allocation-free rule)
__device__ unsigned g_Aph[3 * AW], g_Apl[3 * AW];   // split q,k,v
__device__ unsigned g_Wth[4 * WW], g_Wtl[4 * WW];   // transposed+split Wq,Wk,Wv,Wo
__device__ unsigned g_Qph[AW], g_Qpl[AW];           // head-split packed Q (pre-scaled)
__device__ unsigned g_Kph[AW], g_Kpl[AW];           // head-split packed K
__device__ float    g_Vh[(size_t)BHn * Sn * DEPn];  // head-split V fp32
__device__ unsigned g_Oph[AW], g_Opl[AW];           // attention output, packed

DI unsigned f2tf(float f) {
    unsigned u;
    asm("cvt.rna.tf32.f32 %0, %1;" : "=r"(u) : "f"(f));
    return u;
}
DI void split2(float x, float y, unsigned& h, unsigned& l) {
    __nv_bfloat16 hx = __float2bfloat16(x), hy = __float2bfloat16(y);
    __nv_bfloat162 hp; hp.x = hx; hp.y = hy;
    h = *reinterpret_cast<unsigned*>(&hp);
    __nv_bfloat162 lp;
    lp.x = __float2bfloat16(x - __bfloat162float(hx));
    lp.y = __float2bfloat16(y - __bfloat162float(hy));
    l = *reinterpret_cast<unsigned*>(&lp);
}
DI void mma16(float* c, unsigned a0, unsigned a1, unsigned a2, unsigned a3,
              unsigned b0, unsigned b1) {
    asm volatile(
        "mma.sync.aligned.m16n8k16.row.col.f32.bf16.bf16.f32 "
        "{%0,%1,%2,%3}, {%4,%5,%6,%7}, {%8,%9}, {%0,%1,%2,%3};\n"
        : "+f"(c[0]), "+f"(c[1]), "+f"(c[2]), "+f"(c[3])
        : "r"(a0), "r"(a1), "r"(a2), "r"(a3), "r"(b0), "r"(b1));
}
DI void mma8(float* c, unsigned a0, unsigned a1, unsigned a2, unsigned a3,
             unsigned b0, unsigned b1) {
    asm volatile(
        "mma.sync.aligned.m16n8k8.row.col.f32.tf32.tf32.f32 "
        "{%0,%1,%2,%3}, {%4,%5,%6,%7}, {%8,%9}, {%0,%1,%2,%3};\n"
        : "+f"(c[0]), "+f"(c[1]), "+f"(c[2]), "+f"(c[3])
        : "r"(a0), "r"(a1), "r"(a2), "r"(a3), "r"(b0), "r"(b1));
}

// ---------------------------------------------------------------------------
// Prep: split activations q,k,v into packed bf16x2 hi/lo (no transpose).
// ---------------------------------------------------------------------------
__global__ __launch_bounds__(256) void split_act(const float* __restrict__ q,
                                                 const float* __restrict__ k,
                                                 const float* __restrict__ v) {
    const int z = blockIdx.y;
    const float* src = (z == 0) ? q : (z == 1) ? k : v;
    const size_t i = (size_t)blockIdx.x * 256 + threadIdx.x;  // word-group id
    const size_t base = z * AW + i * 4;
    float4 a = reinterpret_cast<const float4*>(src)[i * 2];
    float4 b = reinterpret_cast<const float4*>(src)[i * 2 + 1];
    split2(a.x, a.y, g_Aph[base + 0], g_Apl[base + 0]);
    split2(a.z, a.w, g_Aph[base + 1], g_Apl[base + 1]);
    split2(b.x, b.y, g_Aph[base + 2], g_Apl[base + 2]);
    split2(b.z, b.w, g_Aph[base + 3], g_Apl[base + 3]);
}

// ---------------------------------------------------------------------------
// Prep: transpose W (K x N) -> Wt[n][kpair], packed bf16x2 hi/lo.
// ---------------------------------------------------------------------------
struct W4 { const float* w[4]; };

__global__ __launch_bounds__(256) void transpose_split(W4 ws) {
    __shared__ float t[32][33];
    const int mat = blockIdx.z, kt = blockIdx.y, nt = blockIdx.x;
    const float* W = ws.w[mat];
    const int tid = threadIdx.x;
    const int rr = tid >> 5, cc = tid & 31;
#pragma unroll
    for (int p = 0; p < 4; ++p)
        t[rr + p * 8][cc] = W[(size_t)(kt * 32 + rr + p * 8) * Dn + nt * 32 + cc];
    __syncthreads();
#pragma unroll
    for (int p = 0; p < 2; ++p) {
        const int idx = tid + p * 256;
        const int n = idx >> 4, kp = idx & 15;
        unsigned h, l;
        split2(t[2 * kp][n], t[2 * kp + 1][n], h, l);
        const size_t o = (size_t)mat * WW + (size_t)(nt * 32 + n) * 512 + kt * 16 + kp;
        g_Wth[o] = h;
        g_Wtl[o] = l;
    }
}

// ---------------------------------------------------------------------------
// Projection GEMM: 128x128x64 tiles, split-bf16 3x, packed operands.
// mode 0: fp32 flat +bias. mode 1: packed head-split (scaled). mode 2: fp32 head-split.
// ---------------------------------------------------------------------------
struct PP3 {
    const unsigned *Ah[3], *Al[3], *Bh[3], *Bl[3];
    const float* bias[3];
    float scale[3];
    int mode[3];
    float* outF[3];
    unsigned *oPh[3], *oPl[3];
};

constexpr int TS = 36;
constexpr int PSMB = 4 * 128 * TS * 4;   // 73,728 B

__global__ __launch_bounds__(256, 2) void proj_gemm(PP3 pp) {
    extern __shared__ unsigned sm[];
    unsigned* Ah = sm;
    unsigned* Al = Ah + 128 * TS;
    unsigned* Bh = Al + 128 * TS;
    unsigned* Bl = Bh + 128 * TS;

    const int z = blockIdx.z;
    const unsigned* gAh = pp.Ah[z];
    const unsigned* gAl = pp.Al[z];
    const unsigned* gBh = pp.Bh[z];
    const unsigned* gBl = pp.Bl[z];
    const float* bias = pp.bias[z];
    const float scale = pp.scale[z];
    const int mode = pp.mode[z];

    const int tid = threadIdx.x, warp = tid >> 5, lane = tid & 31;
    const int gid = lane >> 2, tig = lane & 3;
    const int wm = (warp >> 2) * 64, wn = (warp & 3) * 32;
    const int bm0 = blockIdx.y * 128, bn0 = blockIdx.x * 128;
    const int row = tid >> 1, wq = (tid & 1) * 16;

    float c[4][4][4];
#pragma unroll
    for (int mi = 0; mi < 4; ++mi)
#pragma unroll
        for (int ni = 0; ni < 4; ++ni)
#pragma unroll
            for (int e = 0; e < 4; ++e) c[mi][ni][e] = 0.f;

    for (int kt = 0; kt < 16; ++kt) {
        const uint4* a_h = reinterpret_cast<const uint4*>(gAh + (size_t)(bm0 + row) * 512 + kt * 32 + wq);
        const uint4* a_l = reinterpret_cast<const uint4*>(gAl + (size_t)(bm0 + row) * 512 + kt * 32 + wq);
        const uint4* b_h = reinterpret_cast<const uint4*>(gBh + (size_t)(bn0 + row) * 512 + kt * 32 + wq);
        const uint4* b_l = reinterpret_cast<const uint4*>(gBl + (size_t)(bn0 + row) * 512 + kt * 32 + wq);
#pragma unroll
        for (int u = 0; u < 4; ++u) {
            *reinterpret_cast<uint4*>(&Ah[row * TS + wq + u * 4]) = a_h[u];
            *reinterpret_cast<uint4*>(&Al[row * TS + wq + u * 4]) = a_l[u];
            *reinterpret_cast<uint4*>(&Bh[row * TS + wq + u * 4]) = b_h[u];
            *reinterpret_cast<uint4*>(&Bl[row * TS + wq + u * 4]) = b_l[u];
        }
        __syncthreads();
#pragma unroll
        for (int ks = 0; ks < 4; ++ks) {
            const int kc = ks * 8 + tig;
            unsigned ah[4][4], al[4][4];
#pragma unroll
            for (int mi = 0; mi < 4; ++mi) {
                const int r = wm + mi * 16 + gid;
                ah[mi][0] = Ah[r * TS + kc];       ah[mi][1] = Ah[(r + 8) * TS + kc];
                ah[mi][2] = Ah[r * TS + kc + 4];   ah[mi][3] = Ah[(r + 8) * TS + kc + 4];
                al[mi][0] = Al[r * TS + kc];       al[mi][1] = Al[(r + 8) * TS + kc];
                al[mi][2] = Al[r * TS + kc + 4];   al[mi][3] = Al[(r + 8) * TS + kc + 4];
            }
#pragma unroll
            for (int ni = 0; ni < 4; ++ni) {
                const int n = wn + ni * 8 + gid;
                const unsigned b0h = Bh[n * TS + kc], b1h = Bh[n * TS + kc + 4];
                const unsigned b0l = Bl[n * TS + kc], b1l = Bl[n * TS + kc + 4];
#pragma unroll
                for (int mi = 0; mi < 4; ++mi) {
                    mma16(c[mi][ni], ah[mi][0], ah[mi][1], ah[mi][2], ah[mi][3], b0h, b1h);
                    mma16(c[mi][ni], ah[mi][0], ah[mi][1], ah[mi][2], ah[mi][3], b0l, b1l);
                    mma16(c[mi][ni], al[mi][0], al[mi][1], al[mi][2], al[mi][3], b0h, b1h);
                }
            }
        }
        __syncthreads();
    }

#pragma unroll
    for (int mi = 0; mi < 4; ++mi)
#pragma unroll
        for (int ni = 0; ni < 4; ++ni)
#pragma unroll
            for (int hh = 0; hh < 2; ++hh) {
                const int rowg = bm0 + wm + mi * 16 + gid + hh * 8;
                const int col = bn0 + wn + ni * 8 + tig * 2;
                const float x = (c[mi][ni][hh * 2 + 0] + bias[col]) * scale;
                const float y = (c[mi][ni][hh * 2 + 1] + bias[col + 1]) * scale;
                if (mode == 0) {
                    *reinterpret_cast<float2*>(&pp.outF[z][(size_t)rowg * Dn + col]) =
                        make_float2(x, y);
                } else {
                    const int b = rowg >> 11, s = rowg & (Sn - 1);
                    const int h = col >> 6, d = col & 63;
                    if (mode == 1) {
                        const size_t idx = (((size_t)(b * Hn + h)) * Sn + s) * 32 + (d >> 1);
                        unsigned hw, lw;
                        split2(x, y, hw, lw);
                        pp.oPh[z][idx] = hw;
                        pp.oPl[z][idx] = lw;
                    } else {
                        const size_t idx = (((size_t)(b * Hn + h)) * Sn + s) * 64 + d;
                        *reinterpret_cast<float2*>(&pp.outF[z][idx]) = make_float2(x, y);
                    }
                }
            }
}

// ---------------------------------------------------------------------------
// Fused attention: two-pass flash per (bh, 128-row tile). Writes normalized
// attn once; accumulates O = P@V (tf32) and stores O packed for final GEMM.
// ---------------------------------------------------------------------------
constexpr int QS = 36;
constexpr int OFF_QH = 0, OFF_QL = 4608, OFF_KH = 9216, OFF_KL = 13824;
constexpr int OFF_VT = 18432, OFF_PS = 26880, OFF_MSK = 43776;
constexpr int FSMB = (43776 + 128) * 4;   // 175,616 B

__global__ __launch_bounds__(256, 1) void fmha(const float* __restrict__ mask,
                                               float* __restrict__ attn) {
    extern __shared__ unsigned sm[];
    unsigned* Qh = sm + OFF_QH;
    unsigned* Ql = sm + OFF_QL;
    unsigned* Kh = sm + OFF_KH;
    unsigned* Kl = sm + OFF_KL;
    unsigned* Vt = sm + OFF_VT;
    float* Psf = reinterpret_cast<float*>(sm + OFF_PS);
    float* Msk = reinterpret_cast<float*>(sm + OFF_MSK);

    const int bx = blockIdx.x;
    const int mt = 15 - (bx >> 5);
    const int bh = bx & 31;
    const int b = bh >> 4, h = bh & 15;
    const int tid = threadIdx.x, warp = tid >> 5, lane = tid & 31;
    const int gid = lane >> 2, tig = lane & 3;
    const int wrow = warp * 16;
    const int row = tid >> 1, wq = (tid & 1) * 16;

    // load Q tile (packed hi/lo)
    {
        const size_t qb = ((size_t)bh * Sn + mt * 128 + row) * 32 + wq;
        const uint4* qh4 = reinterpret_cast<const uint4*>(g_Qph + qb);
        const uint4* ql4 = reinterpret_cast<const uint4*>(g_Qpl + qb);
#pragma unroll
        for (int u = 0; u < 4; ++u) {
            *reinterpret_cast<uint4*>(&Qh[row * QS + wq + u * 4]) = qh4[u];
            *reinterpret_cast<uint4*>(&Ql[row * QS + wq + u * 4]) = ql4[u];
        }
    }

    float rm0 = -3.0e38f, rm1 = -3.0e38f, rl0 = 0.f, rl1 = 0.f;

    // ------------------------------- pass 1 -------------------------------
    for (int j = 0; j <= mt; ++j) {
        __syncthreads();
        {
            const size_t kb = ((size_t)bh * Sn + j * 128 + row) * 32 + wq;
            const uint4* kh4 = reinterpret_cast<const uint4*>(g_Kph + kb);
            const uint4* kl4 = reinterpret_cast<const uint4*>(g_Kpl + kb);
#pragma unroll
            for (int u = 0; u < 4; ++u) {
                *reinterpret_cast<uint4*>(&Kh[row * QS + wq + u * 4]) = kh4[u];
                *reinterpret_cast<uint4*>(&Kl[row * QS + wq + u * 4]) = kl4[u];
            }
            if (tid < 128) Msk[tid] = mask[(size_t)b * Sn + j * 128 + tid];
        }
        __syncthreads();

        float c[16][4];
#pragma unroll
        for (int nf = 0; nf < 16; ++nf) { c[nf][0] = c[nf][1] = c[nf][2] = c[nf][3] = 0.f; }
#pragma unroll
        for (int ks = 0; ks < 4; ++ks) {
            const int kc = ks * 8 + tig;
            const int r0 = (wrow + gid) * QS, r1 = (wrow + gid + 8) * QS;
            const unsigned a0h = Qh[r0 + kc], a1h = Qh[r1 + kc];
            const unsigned a2h = Qh[r0 + kc + 4], a3h = Qh[r1 + kc + 4];
            const unsigned a0l = Ql[r0 + kc], a1l = Ql[r1 + kc];
            const unsigned a2l = Ql[r0 + kc + 4], a3l = Ql[r1 + kc + 4];
#pragma unroll
            for (int nf = 0; nf < 16; ++nf) {
                const int nr = (nf * 8 + gid) * QS;
                const unsigned b0h = Kh[nr + kc], b1h = Kh[nr + kc + 4];
                const unsigned b0l = Kl[nr + kc], b1l = Kl[nr + kc + 4];
                mma16(c[nf], a0h, a1h, a2h, a3h, b0h, b1h);
                mma16(c[nf], a0h, a1h, a2h, a3h, b0l, b1l);
                mma16(c[nf], a0l, a1l, a2l, a3l, b0h, b1h);
            }
        }

        float tm0 = -3.0e38f, tm1 = -3.0e38f;
#pragma unroll
        for (int nf = 0; nf < 16; ++nf)
#pragma unroll
            for (int e = 0; e < 4; ++e) {
                const int half = e >> 1;
                const int cl = nf * 8 + tig * 2 + (e & 1);
                const int gcol = j * 128 + cl;
                const int grow = mt * 128 + wrow + gid + half * 8;
                const float pen = fmaxf(Msk[cl], (gcol > grow) ? 1.0f : 0.0f) * -1e17f;
                const float s = c[nf][e] + pen;
                c[nf][e] = s;
                if (half == 0) tm0 = fmaxf(tm0, s);
                else           tm1 = fmaxf(tm1, s);
            }
        {
            const float nm = fmaxf(rm0, tm0);
            float acc = 0.f;
#pragma unroll
            for (int nf = 0; nf < 16; ++nf)
                acc += __expf(c[nf][0] - nm) + __expf(c[nf][1] - nm);
            rl0 = rl0 * __expf(rm0 - nm) + acc;
            rm0 = nm;
        }
        {
            const float nm = fmaxf(rm1, tm1);
            float acc = 0.f;
#pragma unroll
            for (int nf = 0; nf < 16; ++nf)
                acc += __expf(c[nf][2] - nm) + __expf(c[nf][3] - nm);
            rl1 = rl1 * __expf(rm1 - nm) + acc;
            rm1 = nm;
        }
    }

    // cross-lane (tig) stat reduction
#pragma unroll
    for (int off = 1; off < 4; off <<= 1) {
        {
            const float om = __shfl_xor_sync(0xffffffffu, rm0, off);
            const float ol = __shfl_xor_sync(0xffffffffu, rl0, off);
            const float nm = fmaxf(rm0, om);
            rl0 = rl0 * __expf(rm0 - nm) + ol * __expf(om - nm);
            rm0 = nm;
        }
        {
            const float om = __shfl_xor_sync(0xffffffffu, rm1, off);
            const float ol = __shfl_xor_sync(0xffffffffu, rl1, off);
            const float nm = fmaxf(rm1, om);
            rl1 = rl1 * __expf(rm1 - nm) + ol * __expf(om - nm);
            rm1 = nm;
        }
    }
    const float inv0 = 1.f / rl0, inv1 = 1.f / rl1;

    float o[8][4];
#pragma unroll
    for (int nf = 0; nf < 8; ++nf) { o[nf][0] = o[nf][1] = o[nf][2] = o[nf][3] = 0.f; }

    // ------------------------------- pass 2 -------------------------------
    for (int j = 0; j <= mt; ++j) {
        __syncthreads();
        {
            const size_t kb = ((size_t)bh * Sn + j * 128 + row) * 32 + wq;
            const uint4* kh4 = reinterpret_cast<const uint4*>(g_Kph + kb);
            const uint4* kl4 = reinterpret_cast<const uint4*>(g_Kpl + kb);
#pragma unroll
            for (int u = 0; u < 4; ++u) {
                *reinterpret_cast<uint4*>(&Kh[row * QS + wq + u * 4]) = kh4[u];
                *reinterpret_cast<uint4*>(&Kl[row * QS + wq + u * 4]) = kl4[u];
            }
            const int lv = tid >> 1, cq = (tid & 1) * 32;
            const float4* vg = reinterpret_cast<const float4*>(
                g_Vh + ((size_t)bh * Sn + j * 128 + lv) * DEPn + cq);
#pragma unroll
            for (int u = 0; u < 8; ++u) {
                float4 v = vg[u];
                Vt[(cq + u * 4 + 0) * 132 + lv] = f2tf(v.x);
                Vt[(cq + u * 4 + 1) * 132 + lv] = f2tf(v.y);
                Vt[(cq + u * 4 + 2) * 132 + lv] = f2tf(v.z);
                Vt[(cq + u * 4 + 3) * 132 + lv] = f2tf(v.w);
            }
            if (tid < 128) Msk[tid] = mask[(size_t)b * Sn + j * 128 + tid];
        }
        __syncthreads();

        float c[16][4];
#pragma unroll
        for (int nf = 0; nf < 16; ++nf) { c[nf][0] = c[nf][1] = c[nf][2] = c[nf][3] = 0.f; }
#pragma unroll
        for (int ks = 0; ks < 4; ++ks) {
            const int kc = ks * 8 + tig;
            const int r0 = (wrow + gid) * QS, r1 = (wrow + gid + 8) * QS;
            const unsigned a0h = Qh[r0 + kc], a1h = Qh[r1 + kc];
            const unsigned a2h = Qh[r0 + kc + 4], a3h = Qh[r1 + kc + 4];
            const unsigned a0l = Ql[r0 + kc], a1l = Ql[r1 + kc];
            const unsigned a2l = Ql[r0 + kc + 4], a3l = Ql[r1 + kc + 4];
#pragma unroll
            for (int nf = 0; nf < 16; ++nf) {
                const int nr = (nf * 8 + gid) * QS;
                const unsigned b0h = Kh[nr + kc], b1h = Kh[nr + kc + 4];
                const unsigned b0l = Kl[nr + kc], b1l = Kl[nr + kc + 4];
                mma16(c[nf], a0h, a1h, a2h, a3h, b0h, b1h);
                mma16(c[nf], a0h, a1h, a2h, a3h, b0l, b1l);
                mma16(c[nf], a0l, a1l, a2l, a3l, b0h, b1h);
            }
        }

#pragma unroll
        for (int nf = 0; nf < 16; ++nf)
#pragma unroll
            for (int e = 0; e < 4; ++e) {
                const int half = e >> 1;
                const int cl = nf * 8 + tig * 2 + (e & 1);
                const int gcol = j * 128 + cl;
                const int grow = mt * 128 + wrow + gid + half * 8;
                const float pen = fmaxf(Msk[cl], (gcol > grow) ? 1.0f : 0.0f) * -1e17f;
                const float mm = (half == 0) ? rm0 : rm1;
                const float iv = (half == 0) ? inv0 : inv1;
                c[nf][e] = __expf(c[nf][e] + pen - mm) * iv;
            }
        // stage P (warp-private rows)
#pragma unroll
        for (int nf = 0; nf < 16; ++nf)
#pragma unroll
            for (int half = 0; half < 2; ++half)
                *reinterpret_cast<float2*>(
                    &Psf[(wrow + gid + half * 8) * 132 + nf * 8 + tig * 2]) =
                    make_float2(c[nf][half * 2], c[nf][half * 2 + 1]);
        __syncwarp();

        // coalesced attn write (one row per warp-instruction)
        float* attnp = attn + ((size_t)bh * Sn + mt * 128) * Sn + (size_t)j * 128;
#pragma unroll
        for (int u = 0; u < 16; ++u) {
            const int r = wrow + u;
            *reinterpret_cast<float4*>(attnp + (size_t)r * Sn + lane * 4) =
                *reinterpret_cast<const float4*>(&Psf[r * 132 + lane * 4]);
        }

        // O += P @ V (tf32)
#pragma unroll
        for (int ks = 0; ks < 16; ++ks) {
            const int kc = ks * 8 + tig;
            const unsigned a0 = f2tf(Psf[(wrow + gid) * 132 + kc]);
            const unsigned a1 = f2tf(Psf[(wrow + gid + 8) * 132 + kc]);
            const unsigned a2 = f2tf(Psf[(wrow + gid) * 132 + kc + 4]);
            const unsigned a3 = f2tf(Psf[(wrow + gid + 8) * 132 + kc + 4]);
#pragma unroll
            for (int nf = 0; nf < 8; ++nf) {
                const unsigned b0 = Vt[(nf * 8 + gid) * 132 + kc];
                const unsigned b1 = Vt[(nf * 8 + gid) * 132 + kc + 4];
                mma8(o[nf], a0, a1, a2, a3, b0, b1);
            }
        }
    }

    // zero-fill fully-masked tiles
    for (int j = mt + 1; j < 16; ++j) {
        float* attnp = attn + ((size_t)bh * Sn + mt * 128) * Sn + (size_t)j * 128;
        const float4 z4 = make_float4(0.f, 0.f, 0.f, 0.f);
#pragma unroll
        for (int u = 0; u < 16; ++u) {
            const int r = wrow + u;
            *reinterpret_cast<float4*>(attnp + (size_t)r * Sn + lane * 4) = z4;
        }
    }

    // O epilogue: packed bf16 hi/lo for the final projection
#pragma unroll
    for (int nf = 0; nf < 8; ++nf)
#pragma unroll
        for (int hh = 0; hh < 2; ++hh) {
            const int s = mt * 128 + wrow + gid + hh * 8;
            const size_t idx = ((size_t)(b * Sn + s)) * 512 + h * 32 + nf * 4 + tig;
            unsigned hw, lw;
            split2(o[nf][hh * 2], o[nf][hh * 2 + 1], hw, lw);
            g_Oph[idx] = hw;
            g_Opl[idx] = lw;
        }
}

// ---------------------------------------------------------------------------
extern "C" void kernel_launch(void* const* d_in, const int* in_sizes, int n_in,
                              void* d_out, int out_size) {
    const float* v    = (const float*)d_in[0];
    const float* k    = (const float*)d_in[1];
    const float* q    = (const float*)d_in[2];
    const float* mask = (const float*)d_in[3];
    const float* Wq = (const float*)d_in[4],  *bq = (const float*)d_in[5];
    const float* Wk = (const float*)d_in[6],  *bk = (const float*)d_in[7];
    const float* Wv = (const float*)d_in[8],  *bv = (const float*)d_in[9];
    const float* Wo = (const float*)d_in[10], *bo = (const float*)d_in[11];

    float* out  = (float*)d_out;
    float* attn = out + OUT_ELEMS;

    void *aph, *apl, *wth, *wtl, *qph, *qpl, *kph, *kpl, *vh, *oph, *opl;
    cudaGetSymbolAddress(&aph, g_Aph);
    cudaGetSymbolAddress(&apl, g_Apl);
    cudaGetSymbolAddress(&wth, g_Wth);
    cudaGetSymbolAddress(&wtl, g_Wtl);
    cudaGetSymbolAddress(&qph, g_Qph);
    cudaGetSymbolAddress(&qpl, g_Qpl);
    cudaGetSymbolAddress(&kph, g_Kph);
    cudaGetSymbolAddress(&kpl, g_Kpl);
    cudaGetSymbolAddress(&vh, g_Vh);
    cudaGetSymbolAddress(&oph, g_Oph);
    cudaGetSymbolAddress(&opl, g_Opl);

    cudaFuncSetAttribute(proj_gemm, cudaFuncAttributeMaxDynamicSharedMemorySize, PSMB);
    cudaFuncSetAttribute(fmha, cudaFuncAttributeMaxDynamicSharedMemorySize, FSMB);

    split_act<<<dim3((unsigned)(AW / 4 / 256), 3), 256>>>(q, k, v);
    W4 ws;
    ws.w[0] = Wq; ws.w[1] = Wk; ws.w[2] = Wv; ws.w[3] = Wo;
    transpose_split<<<dim3(32, 32, 4), 256>>>(ws);

    PP3 p1;
    for (int z = 0; z < 3; ++z) {
        p1.Ah[z] = (const unsigned*)aph + (size_t)z * AW;
        p1.Al[z] = (const unsigned*)apl + (size_t)z * AW;
        p1.Bh[z] = (const unsigned*)wth + (size_t)z * WW;
        p1.Bl[z] = (const unsigned*)wtl + (size_t)z * WW;
        p1.outF[z] = nullptr;
        p1.oPh[z] = nullptr;
        p1.oPl[z] = nullptr;
    }
    p1.bias[0] = bq; p1.scale[0] = 0.125f; p1.mode[0] = 1;
    p1.oPh[0] = (unsigned*)qph; p1.oPl[0] = (unsigned*)qpl;
    p1.bias[1] = bk; p1.scale[1] = 1.0f;   p1.mode[1] = 1;
    p1.oPh[1] = (unsigned*)kph; p1.oPl[1] = (unsigned*)kpl;
    p1.bias[2] = bv; p1.scale[2] = 1.0f;   p1.mode[2] = 2;
    p1.outF[2] = (float*)vh;
    proj_gemm<<<dim3(8, 32, 3), 256, PSMB>>>(p1);

    fmha<<<512, 256, FSMB>>>(mask, attn);

    PP3 p2;
    for (int z = 0; z < 3; ++z) {
        p2.Ah[z] = (const unsigned*)oph;
        p2.Al[z] = (const unsigned*)opl;
        p2.Bh[z] = (const unsigned*)wth + (size_t)3 * WW;
        p2.Bl[z] = (const unsigned*)wtl + (size_t)3 * WW;
        p2.bias[z] = bo;
        p2.scale[z] = 1.0f;
        p2.mode[z] = 0;
        p2.outF[z] = out;
        p2.oPh[z] = nullptr;
        p2.oPl[z] = nullptr;
    }
    proj_gemm<<<dim3(8, 32, 1), 256, PSMB>>>(p2);
}

// round 12
// speedup vs baseline: 2.2880x; 1.0955x over previous
#include <cuda_runtime.h>
#include <cuda_bf16.h>

#define DI __device__ __forceinline__

constexpr int Bn = 2, Sn = 2048, Dn = 1024, Hn = 16, DEPn = 64, BHn = 32, Mn = 4096;
constexpr long long OUT_ELEMS = (long long)Mn * Dn;
constexpr size_t AW = (size_t)Mn * 512;   // activation words per half-matrix
constexpr size_t WW = (size_t)Dn * 512;   // weight words per half-matrix

// scratch (__device__ globals: allocation-free rule)
__device__ unsigned g_Aph[3 * AW], g_Apl[3 * AW];   // split q,k,v
__device__ unsigned g_Wth[4 * WW], g_Wtl[4 * WW];   // transposed+split Wq,Wk,Wv,Wo
__device__ unsigned g_Qph[AW], g_Qpl[AW];           // head-split packed Q (pre-scaled)
__device__ unsigned g_Kph[AW], g_Kpl[AW];           // head-split packed K
__device__ float    g_Vt[(size_t)BHn * DEPn * Sn];  // V TRANSPOSED (bh, d, s) fp32
__device__ unsigned g_Oph[AW], g_Opl[AW];           // attention output, packed

DI void split2(float x, float y, unsigned& h, unsigned& l) {
    __nv_bfloat16 hx = __float2bfloat16(x), hy = __float2bfloat16(y);
    __nv_bfloat162 hp; hp.x = hx; hp.y = hy;
    h = *reinterpret_cast<unsigned*>(&hp);
    __nv_bfloat162 lp;
    lp.x = __float2bfloat16(x - __bfloat162float(hx));
    lp.y = __float2bfloat16(y - __bfloat162float(hy));
    l = *reinterpret_cast<unsigned*>(&lp);
}
DI void mma16(float* c, unsigned a0, unsigned a1, unsigned a2, unsigned a3,
              unsigned b0, unsigned b1) {
    asm volatile(
        "mma.sync.aligned.m16n8k16.row.col.f32.bf16.bf16.f32 "
        "{%0,%1,%2,%3}, {%4,%5,%6,%7}, {%8,%9}, {%0,%1,%2,%3};\n"
        : "+f"(c[0]), "+f"(c[1]), "+f"(c[2]), "+f"(c[3])
        : "r"(a0), "r"(a1), "r"(a2), "r"(a3), "r"(b0), "r"(b1));
}
DI void ldsm4(unsigned* r, unsigned addr) {
    asm volatile(
        "ldmatrix.sync.aligned.m8n8.x4.shared.b16 {%0,%1,%2,%3}, [%4];"
        : "=r"(r[0]), "=r"(r[1]), "=r"(r[2]), "=r"(r[3]) : "r"(addr));
}

// ---------------------------------------------------------------------------
// Prep: split activations q,k,v into packed bf16x2 hi/lo (no transpose).
// ---------------------------------------------------------------------------
__global__ __launch_bounds__(256) void split_act(const float* __restrict__ q,
                                                 const float* __restrict__ k,
                                                 const float* __restrict__ v) {
    const int z = blockIdx.y;
    const float* src = (z == 0) ? q : (z == 1) ? k : v;
    const size_t i = (size_t)blockIdx.x * 256 + threadIdx.x;
    const size_t base = z * AW + i * 4;
    float4 a = reinterpret_cast<const float4*>(src)[i * 2];
    float4 b = reinterpret_cast<const float4*>(src)[i * 2 + 1];
    split2(a.x, a.y, g_Aph[base + 0], g_Apl[base + 0]);
    split2(a.z, a.w, g_Aph[base + 1], g_Apl[base + 1]);
    split2(b.x, b.y, g_Aph[base + 2], g_Apl[base + 2]);
    split2(b.z, b.w, g_Aph[base + 3], g_Apl[base + 3]);
}

// ---------------------------------------------------------------------------
// Prep: transpose W (K x N) -> Wt[n][kpair], packed bf16x2 hi/lo.
// ---------------------------------------------------------------------------
struct W4 { const float* w[4]; };

__global__ __launch_bounds__(256) void transpose_split(W4 ws) {
    __shared__ float t[32][33];
    const int mat = blockIdx.z, kt = blockIdx.y, nt = blockIdx.x;
    const float* W = ws.w[mat];
    const int tid = threadIdx.x;
    const int rr = tid >> 5, cc = tid & 31;
#pragma unroll
    for (int p = 0; p < 4; ++p)
        t[rr + p * 8][cc] = W[(size_t)(kt * 32 + rr + p * 8) * Dn + nt * 32 + cc];
    __syncthreads();
#pragma unroll
    for (int p = 0; p < 2; ++p) {
        const int idx = tid + p * 256;
        const int n = idx >> 4, kp = idx & 15;
        unsigned h, l;
        split2(t[2 * kp][n], t[2 * kp + 1][n], h, l);
        const size_t o = (size_t)mat * WW + (size_t)(nt * 32 + n) * 512 + kt * 16 + kp;
        g_Wth[o] = h;
        g_Wtl[o] = l;
    }
}

// ---------------------------------------------------------------------------
// Projection GEMM: 128x128x64 tiles, split-bf16 3x, ldmatrix fragment loads.
// mode 0: fp32 flat. mode 1: packed head-split (scaled). mode 2: fp32 V^T.
// ---------------------------------------------------------------------------
struct PP3 {
    const unsigned *Ah[3], *Al[3], *Bh[3], *Bl[3];
    const float* bias[3];
    float scale[3];
    int mode[3];
    float* outF[3];
    unsigned *oPh[3], *oPl[3];
};

constexpr int TS = 36;
constexpr int PSMB = 4 * 128 * TS * 4;   // 73,728 B

__global__ __launch_bounds__(256, 2) void proj_gemm(PP3 pp) {
    extern __shared__ unsigned sm[];
    unsigned* Ah = sm;
    unsigned* Al = Ah + 128 * TS;
    unsigned* Bh = Al + 128 * TS;
    unsigned* Bl = Bh + 128 * TS;

    const int z = blockIdx.z;
    const unsigned* gAh = pp.Ah[z];
    const unsigned* gAl = pp.Al[z];
    const unsigned* gBh = pp.Bh[z];
    const unsigned* gBl = pp.Bl[z];
    const float* bias = pp.bias[z];
    const float scale = pp.scale[z];
    const int mode = pp.mode[z];

    const int tid = threadIdx.x, warp = tid >> 5, lane = tid & 31;
    const int gid = lane >> 2, tig = lane & 3;
    const int wm = (warp >> 2) * 64, wn = (warp & 3) * 32;
    const int bm0 = blockIdx.y * 128, bn0 = blockIdx.x * 128;
    const int row = tid >> 1, wq = (tid & 1) * 16;

    const unsigned sAh = (unsigned)__cvta_generic_to_shared(Ah);
    const unsigned sAl = (unsigned)__cvta_generic_to_shared(Al);
    const unsigned sBh = (unsigned)__cvta_generic_to_shared(Bh);
    const unsigned sBl = (unsigned)__cvta_generic_to_shared(Bl);
    // ldmatrix per-lane base offsets (bytes)
    const unsigned aoff = ((wm + (lane & 15)) * TS + ((lane >> 4) << 2)) * 4;
    const unsigned boff =
        ((wn + (lane & 7) + ((lane & 16) ? 8 : 0)) * TS + (((lane >> 3) & 1) << 2)) * 4;

    float c[4][4][4];
#pragma unroll
    for (int mi = 0; mi < 4; ++mi)
#pragma unroll
        for (int ni = 0; ni < 4; ++ni)
#pragma unroll
            for (int e = 0; e < 4; ++e) c[mi][ni][e] = 0.f;

    for (int kt = 0; kt < 16; ++kt) {
        const uint4* a_h = reinterpret_cast<const uint4*>(gAh + (size_t)(bm0 + row) * 512 + kt * 32 + wq);
        const uint4* a_l = reinterpret_cast<const uint4*>(gAl + (size_t)(bm0 + row) * 512 + kt * 32 + wq);
        const uint4* b_h = reinterpret_cast<const uint4*>(gBh + (size_t)(bn0 + row) * 512 + kt * 32 + wq);
        const uint4* b_l = reinterpret_cast<const uint4*>(gBl + (size_t)(bn0 + row) * 512 + kt * 32 + wq);
#pragma unroll
        for (int u = 0; u < 4; ++u) {
            *reinterpret_cast<uint4*>(&Ah[row * TS + wq + u * 4]) = a_h[u];
            *reinterpret_cast<uint4*>(&Al[row * TS + wq + u * 4]) = a_l[u];
            *reinterpret_cast<uint4*>(&Bh[row * TS + wq + u * 4]) = b_h[u];
            *reinterpret_cast<uint4*>(&Bl[row * TS + wq + u * 4]) = b_l[u];
        }
        __syncthreads();
#pragma unroll
        for (int ks = 0; ks < 4; ++ks) {
            unsigned ah[4][4], al[4][4], bh2[2][4], bl2[2][4];
#pragma unroll
            for (int mi = 0; mi < 4; ++mi) {
                ldsm4(ah[mi], sAh + aoff + mi * (16 * TS * 4) + ks * 32);
                ldsm4(al[mi], sAl + aoff + mi * (16 * TS * 4) + ks * 32);
            }
#pragma unroll
            for (int n2 = 0; n2 < 2; ++n2) {
                ldsm4(bh2[n2], sBh + boff + n2 * (16 * TS * 4) + ks * 32);
                ldsm4(bl2[n2], sBl + boff + n2 * (16 * TS * 4) + ks * 32);
            }
#pragma unroll
            for (int ni = 0; ni < 4; ++ni) {
                const unsigned b0h = bh2[ni >> 1][(ni & 1) * 2];
                const unsigned b1h = bh2[ni >> 1][(ni & 1) * 2 + 1];
                const unsigned b0l = bl2[ni >> 1][(ni & 1) * 2];
                const unsigned b1l = bl2[ni >> 1][(ni & 1) * 2 + 1];
#pragma unroll
                for (int mi = 0; mi < 4; ++mi) {
                    mma16(c[mi][ni], ah[mi][0], ah[mi][1], ah[mi][2], ah[mi][3], b0h, b1h);
                    mma16(c[mi][ni], ah[mi][0], ah[mi][1], ah[mi][2], ah[mi][3], b0l, b1l);
                    mma16(c[mi][ni], al[mi][0], al[mi][1], al[mi][2], al[mi][3], b0h, b1h);
                }
            }
        }
        __syncthreads();
    }

#pragma unroll
    for (int mi = 0; mi < 4; ++mi)
#pragma unroll
        for (int ni = 0; ni < 4; ++ni)
#pragma unroll
            for (int hh = 0; hh < 2; ++hh) {
                const int rowg = bm0 + wm + mi * 16 + gid + hh * 8;
                const int col = bn0 + wn + ni * 8 + tig * 2;
                const float x = (c[mi][ni][hh * 2 + 0] + bias[col]) * scale;
                const float y = (c[mi][ni][hh * 2 + 1] + bias[col + 1]) * scale;
                if (mode == 0) {
                    *reinterpret_cast<float2*>(&pp.outF[z][(size_t)rowg * Dn + col]) =
                        make_float2(x, y);
                } else {
                    const int b = rowg >> 11, s = rowg & (Sn - 1);
                    const int h = col >> 6, d = col & 63;
                    if (mode == 1) {
                        const size_t idx = (((size_t)(b * Hn + h)) * Sn + s) * 32 + (d >> 1);
                        unsigned hw, lw;
                        split2(x, y, hw, lw);
                        pp.oPh[z][idx] = hw;
                        pp.oPl[z][idx] = lw;
                    } else {  // mode 2: V transposed (bh, d, s)
                        const size_t idx = (((size_t)(b * Hn + h)) * DEPn + d) * Sn + s;
                        pp.outF[z][idx] = x;
                        pp.outF[z][idx + Sn] = y;
                    }
                }
            }
}

// ---------------------------------------------------------------------------
// Fused attention: two-pass flash per (bh, 128-row tile). ldmatrix fragments,
// PV fed straight from softmax registers (split-bf16 3x), attn written from
// registers. V comes pre-transposed from the projection.
// ---------------------------------------------------------------------------
constexpr int QS = 36, VS = 68;
constexpr int OFF_QH = 0, OFF_QL = 4608, OFF_KH = 9216, OFF_KL = 13824;
constexpr int OFF_VTH = 18432, OFF_VTL = 22784, OFF_MSK = 27136;
constexpr int FSMB = (27136 + 128) * 4;   // 109,056 B

__global__ __launch_bounds__(256, 1) void fmha(const float* __restrict__ mask,
                                               float* __restrict__ attn) {
    extern __shared__ unsigned sm[];
    unsigned* Qh = sm + OFF_QH;
    unsigned* Ql = sm + OFF_QL;
    unsigned* Kh = sm + OFF_KH;
    unsigned* Kl = sm + OFF_KL;
    unsigned* Vth = sm + OFF_VTH;
    unsigned* Vtl = sm + OFF_VTL;
    float* Msk = reinterpret_cast<float*>(sm + OFF_MSK);

    const int bx = blockIdx.x;
    const int mt = 15 - (bx >> 5);
    const int bh = bx & 31;
    const int b = bh >> 4, h = bh & 15;
    const int tid = threadIdx.x, warp = tid >> 5, lane = tid & 31;
    const int gid = lane >> 2, tig = lane & 3;
    const int wrow = warp * 16;
    const int row = tid >> 1, wq = (tid & 1) * 16;

    const unsigned sQh = (unsigned)__cvta_generic_to_shared(Qh);
    const unsigned sQl = (unsigned)__cvta_generic_to_shared(Ql);
    const unsigned sKh = (unsigned)__cvta_generic_to_shared(Kh);
    const unsigned sKl = (unsigned)__cvta_generic_to_shared(Kl);
    const unsigned sVh = (unsigned)__cvta_generic_to_shared(Vth);
    const unsigned sVl = (unsigned)__cvta_generic_to_shared(Vtl);
    const unsigned aoff = ((wrow + (lane & 15)) * QS + ((lane >> 4) << 2)) * 4;
    const unsigned koff =
        (((lane & 7) + ((lane & 16) ? 8 : 0)) * QS + (((lane >> 3) & 1) << 2)) * 4;
    const unsigned voff =
        (((lane & 7) + ((lane & 16) ? 8 : 0)) * VS + (((lane >> 3) & 1) << 2)) * 4;

    // load Q tile (packed hi/lo)
    {
        const size_t qb = ((size_t)bh * Sn + mt * 128 + row) * 32 + wq;
        const uint4* qh4 = reinterpret_cast<const uint4*>(g_Qph + qb);
        const uint4* ql4 = reinterpret_cast<const uint4*>(g_Qpl + qb);
#pragma unroll
        for (int u = 0; u < 4; ++u) {
            *reinterpret_cast<uint4*>(&Qh[row * QS + wq + u * 4]) = qh4[u];
            *reinterpret_cast<uint4*>(&Ql[row * QS + wq + u * 4]) = ql4[u];
        }
    }

    float rm0 = -3.0e38f, rm1 = -3.0e38f, rl0 = 0.f, rl1 = 0.f;

    // ------------------------------- pass 1 -------------------------------
    for (int j = 0; j <= mt; ++j) {
        __syncthreads();
        {
            const size_t kb = ((size_t)bh * Sn + j * 128 + row) * 32 + wq;
            const uint4* kh4 = reinterpret_cast<const uint4*>(g_Kph + kb);
            const uint4* kl4 = reinterpret_cast<const uint4*>(g_Kpl + kb);
#pragma unroll
            for (int u = 0; u < 4; ++u) {
                *reinterpret_cast<uint4*>(&Kh[row * QS + wq + u * 4]) = kh4[u];
                *reinterpret_cast<uint4*>(&Kl[row * QS + wq + u * 4]) = kl4[u];
            }
            if (tid < 128) Msk[tid] = mask[(size_t)b * Sn + j * 128 + tid];
        }
        __syncthreads();

        float c[16][4];
#pragma unroll
        for (int nf = 0; nf < 16; ++nf) { c[nf][0] = c[nf][1] = c[nf][2] = c[nf][3] = 0.f; }
#pragma unroll
        for (int ks = 0; ks < 4; ++ks) {
            unsigned ah[4], al[4];
            ldsm4(ah, sQh + aoff + ks * 32);
            ldsm4(al, sQl + aoff + ks * 32);
#pragma unroll
            for (int n2 = 0; n2 < 8; ++n2) {
                unsigned kh[4], kl[4];
                ldsm4(kh, sKh + koff + n2 * (16 * QS * 4) + ks * 32);
                ldsm4(kl, sKl + koff + n2 * (16 * QS * 4) + ks * 32);
                mma16(c[2 * n2], ah[0], ah[1], ah[2], ah[3], kh[0], kh[1]);
                mma16(c[2 * n2], ah[0], ah[1], ah[2], ah[3], kl[0], kl[1]);
                mma16(c[2 * n2], al[0], al[1], al[2], al[3], kh[0], kh[1]);
                mma16(c[2 * n2 + 1], ah[0], ah[1], ah[2], ah[3], kh[2], kh[3]);
                mma16(c[2 * n2 + 1], ah[0], ah[1], ah[2], ah[3], kl[2], kl[3]);
                mma16(c[2 * n2 + 1], al[0], al[1], al[2], al[3], kh[2], kh[3]);
            }
        }

        float tm0 = -3.0e38f, tm1 = -3.0e38f;
#pragma unroll
        for (int nf = 0; nf < 16; ++nf)
#pragma unroll
            for (int e = 0; e < 4; ++e) {
                const int half = e >> 1;
                const int cl = nf * 8 + tig * 2 + (e & 1);
                const int gcol = j * 128 + cl;
                const int grow = mt * 128 + wrow + gid + half * 8;
                const float pen = fmaxf(Msk[cl], (gcol > grow) ? 1.0f : 0.0f) * -1e17f;
                const float s = c[nf][e] + pen;
                c[nf][e] = s;
                if (half == 0) tm0 = fmaxf(tm0, s);
                else           tm1 = fmaxf(tm1, s);
            }
        {
            const float nm = fmaxf(rm0, tm0);
            float acc = 0.f;
#pragma unroll
            for (int nf = 0; nf < 16; ++nf)
                acc += __expf(c[nf][0] - nm) + __expf(c[nf][1] - nm);
            rl0 = rl0 * __expf(rm0 - nm) + acc;
            rm0 = nm;
        }
        {
            const float nm = fmaxf(rm1, tm1);
            float acc = 0.f;
#pragma unroll
            for (int nf = 0; nf < 16; ++nf)
                acc += __expf(c[nf][2] - nm) + __expf(c[nf][3] - nm);
            rl1 = rl1 * __expf(rm1 - nm) + acc;
            rm1 = nm;
        }
    }

    // cross-lane (tig) stat reduction
#pragma unroll
    for (int off = 1; off < 4; off <<= 1) {
        {
            const float om = __shfl_xor_sync(0xffffffffu, rm0, off);
            const float ol = __shfl_xor_sync(0xffffffffu, rl0, off);
            const float nm = fmaxf(rm0, om);
            rl0 = rl0 * __expf(rm0 - nm) + ol * __expf(om - nm);
            rm0 = nm;
        }
        {
            const float om = __shfl_xor_sync(0xffffffffu, rm1, off);
            const float ol = __shfl_xor_sync(0xffffffffu, rl1, off);
            const float nm = fmaxf(rm1, om);
            rl1 = rl1 * __expf(rm1 - nm) + ol * __expf(om - nm);
            rm1 = nm;
        }
    }
    const float inv0 = 1.f / rl0, inv1 = 1.f / rl1;

    float o[8][4];
#pragma unroll
    for (int nf = 0; nf < 8; ++nf) { o[nf][0] = o[nf][1] = o[nf][2] = o[nf][3] = 0.f; }

    // ------------------------------- pass 2 -------------------------------
    for (int j = 0; j <= mt; ++j) {
        __syncthreads();
        {
            const size_t kb = ((size_t)bh * Sn + j * 128 + row) * 32 + wq;
            const uint4* kh4 = reinterpret_cast<const uint4*>(g_Kph + kb);
            const uint4* kl4 = reinterpret_cast<const uint4*>(g_Kpl + kb);
#pragma unroll
            for (int u = 0; u < 4; ++u) {
                *reinterpret_cast<uint4*>(&Kh[row * QS + wq + u * 4]) = kh4[u];
                *reinterpret_cast<uint4*>(&Kl[row * QS + wq + u * 4]) = kl4[u];
            }
            // V^T tile: 64 d-rows x 128 s (=64 words); float4 loads cover all
            // 4096 words: 8 iters x 256 threads x 2 words.
#pragma unroll
            for (int u = 0; u < 8; ++u) {
                const int flat = tid + u * 256;      // 0..2047
                const int d = flat >> 5;             // 0..63
                const int g = flat & 31;             // float4 group within row
                const float4 vv = *reinterpret_cast<const float4*>(
                    g_Vt + ((size_t)bh * DEPn + d) * Sn + j * 128 + 4 * g);
                unsigned h0, l0, h1, l1;
                split2(vv.x, vv.y, h0, l0);
                split2(vv.z, vv.w, h1, l1);
                Vth[d * VS + 2 * g]     = h0;
                Vth[d * VS + 2 * g + 1] = h1;
                Vtl[d * VS + 2 * g]     = l0;
                Vtl[d * VS + 2 * g + 1] = l1;
            }
            if (tid < 128) Msk[tid] = mask[(size_t)b * Sn + j * 128 + tid];
        }
        __syncthreads();

        float c[16][4];
#pragma unroll
        for (int nf = 0; nf < 16; ++nf) { c[nf][0] = c[nf][1] = c[nf][2] = c[nf][3] = 0.f; }
#pragma unroll
        for (int ks = 0; ks < 4; ++ks) {
            unsigned ah[4], al[4];
            ldsm4(ah, sQh + aoff + ks * 32);
            ldsm4(al, sQl + aoff + ks * 32);
#pragma unroll
            for (int n2 = 0; n2 < 8; ++n2) {
                unsigned kh[4], kl[4];
                ldsm4(kh, sKh + koff + n2 * (16 * QS * 4) + ks * 32);
                ldsm4(kl, sKl + koff + n2 * (16 * QS * 4) + ks * 32);
                mma16(c[2 * n2], ah[0], ah[1], ah[2], ah[3], kh[0], kh[1]);
                mma16(c[2 * n2], ah[0], ah[1], ah[2], ah[3], kl[0], kl[1]);
                mma16(c[2 * n2], al[0], al[1], al[2], al[3], kh[0], kh[1]);
                mma16(c[2 * n2 + 1], ah[0], ah[1], ah[2], ah[3], kh[2], kh[3]);
                mma16(c[2 * n2 + 1], ah[0], ah[1], ah[2], ah[3], kl[2], kl[3]);
                mma16(c[2 * n2 + 1], al[0], al[1], al[2], al[3], kh[2], kh[3]);
            }
        }

        // softmax (exact, consistent with pass 1)
#pragma unroll
        for (int nf = 0; nf < 16; ++nf)
#pragma unroll
            for (int e = 0; e < 4; ++e) {
                const int half = e >> 1;
                const int cl = nf * 8 + tig * 2 + (e & 1);
                const int gcol = j * 128 + cl;
                const int grow = mt * 128 + wrow + gid + half * 8;
                const float pen = fmaxf(Msk[cl], (gcol > grow) ? 1.0f : 0.0f) * -1e17f;
                const float mm = (half == 0) ? rm0 : rm1;
                const float iv = (half == 0) ? inv0 : inv1;
                c[nf][e] = __expf(c[nf][e] + pen - mm) * iv;
            }

        // attn write straight from registers (8 rows x 32B full sectors / store)
        float* attnp = attn + ((size_t)bh * Sn + mt * 128) * Sn + (size_t)j * 128;
#pragma unroll
        for (int nf = 0; nf < 16; ++nf)
#pragma unroll
            for (int half = 0; half < 2; ++half) {
                const int r = wrow + gid + half * 8;
                *reinterpret_cast<float2*>(attnp + (size_t)r * Sn + nf * 8 + tig * 2) =
                    make_float2(c[nf][half * 2], c[nf][half * 2 + 1]);
            }

        // O += P @ V : A-fragments split from registers, 3-term bf16
#pragma unroll
        for (int cH = 0; cH < 8; ++cH) {
            unsigned pah[4], pal[4];
            split2(c[2 * cH][0], c[2 * cH][1], pah[0], pal[0]);
            split2(c[2 * cH][2], c[2 * cH][3], pah[1], pal[1]);
            split2(c[2 * cH + 1][0], c[2 * cH + 1][1], pah[2], pal[2]);
            split2(c[2 * cH + 1][2], c[2 * cH + 1][3], pah[3], pal[3]);
#pragma unroll
            for (int n2 = 0; n2 < 4; ++n2) {
                unsigned vh[4], vl[4];
                ldsm4(vh, sVh + voff + n2 * (16 * VS * 4) + cH * 32);
                ldsm4(vl, sVl + voff + n2 * (16 * VS * 4) + cH * 32);
                mma16(o[2 * n2], pah[0], pah[1], pah[2], pah[3], vh[0], vh[1]);
                mma16(o[2 * n2], pah[0], pah[1], pah[2], pah[3], vl[0], vl[1]);
                mma16(o[2 * n2], pal[0], pal[1], pal[2], pal[3], vh[0], vh[1]);
                mma16(o[2 * n2 + 1], pah[0], pah[1], pah[2], pah[3], vh[2], vh[3]);
                mma16(o[2 * n2 + 1], pah[0], pah[1], pah[2], pah[3], vl[2], vl[3]);
                mma16(o[2 * n2 + 1], pal[0], pal[1], pal[2], pal[3], vh[2], vh[3]);
            }
        }
    }

    // zero-fill fully-masked tiles
    for (int j = mt + 1; j < 16; ++j) {
        float* attnp = attn + ((size_t)bh * Sn + mt * 128) * Sn + (size_t)j * 128;
        const float4 z4 = make_float4(0.f, 0.f, 0.f, 0.f);
#pragma unroll
        for (int u = 0; u < 16; ++u) {
            const int r = wrow + u;
            *reinterpret_cast<float4*>(attnp + (size_t)r * Sn + lane * 4) = z4;
        }
    }

    // O epilogue: packed bf16 hi/lo for the final projection
#pragma unroll
    for (int nf = 0; nf < 8; ++nf)
#pragma unroll
        for (int hh = 0; hh < 2; ++hh) {
            const int s = mt * 128 + wrow + gid + hh * 8;
            const size_t idx = ((size_t)(b * Sn + s)) * 512 + h * 32 + nf * 4 + tig;
            unsigned hw, lw;
            split2(o[nf][hh * 2], o[nf][hh * 2 + 1], hw, lw);
            g_Oph[idx] = hw;
            g_Opl[idx] = lw;
        }
}

// ---------------------------------------------------------------------------
extern "C" void kernel_launch(void* const* d_in, const int* in_sizes, int n_in,
                              void* d_out, int out_size) {
    const float* v    = (const float*)d_in[0];
    const float* k    = (const float*)d_in[1];
    const float* q    = (const float*)d_in[2];
    const float* mask = (const float*)d_in[3];
    const float* Wq = (const float*)d_in[4],  *bq = (const float*)d_in[5];
    const float* Wk = (const float*)d_in[6],  *bk = (const float*)d_in[7];
    const float* Wv = (const float*)d_in[8],  *bv = (const float*)d_in[9];
    const float* Wo = (const float*)d_in[10], *bo = (const float*)d_in[11];

    float* out  = (float*)d_out;
    float* attn = out + OUT_ELEMS;

    void *aph, *apl, *wth, *wtl, *qph, *qpl, *kph, *kpl, *vt, *oph, *opl;
    cudaGetSymbolAddress(&aph, g_Aph);
    cudaGetSymbolAddress(&apl, g_Apl);
    cudaGetSymbolAddress(&wth, g_Wth);
    cudaGetSymbolAddress(&wtl, g_Wtl);
    cudaGetSymbolAddress(&qph, g_Qph);
    cudaGetSymbolAddress(&qpl, g_Qpl);
    cudaGetSymbolAddress(&kph, g_Kph);
    cudaGetSymbolAddress(&kpl, g_Kpl);
    cudaGetSymbolAddress(&vt, g_Vt);
    cudaGetSymbolAddress(&oph, g_Oph);
    cudaGetSymbolAddress(&opl, g_Opl);

    cudaFuncSetAttribute(proj_gemm, cudaFuncAttributeMaxDynamicSharedMemorySize, PSMB);
    cudaFuncSetAttribute(fmha, cudaFuncAttributeMaxDynamicSharedMemorySize, FSMB);

    split_act<<<dim3((unsigned)(AW / 4 / 256), 3), 256>>>(q, k, v);
    W4 ws;
    ws.w[0] = Wq; ws.w[1] = Wk; ws.w[2] = Wv; ws.w[3] = Wo;
    transpose_split<<<dim3(32, 32, 4), 256>>>(ws);

    PP3 p1;
    for (int z = 0; z < 3; ++z) {
        p1.Ah[z] = (const unsigned*)aph + (size_t)z * AW;
        p1.Al[z] = (const unsigned*)apl + (size_t)z * AW;
        p1.Bh[z] = (const unsigned*)wth + (size_t)z * WW;
        p1.Bl[z] = (const unsigned*)wtl + (size_t)z * WW;
        p1.outF[z] = nullptr;
        p1.oPh[z] = nullptr;
        p1.oPl[z] = nullptr;
    }
    p1.bias[0] = bq; p1.scale[0] = 0.125f; p1.mode[0] = 1;
    p1.oPh[0] = (unsigned*)qph; p1.oPl[0] = (unsigned*)qpl;
    p1.bias[1] = bk; p1.scale[1] = 1.0f;   p1.mode[1] = 1;
    p1.oPh[1] = (unsigned*)kph; p1.oPl[1] = (unsigned*)kpl;
    p1.bias[2] = bv; p1.scale[2] = 1.0f;   p1.mode[2] = 2;
    p1.outF[2] = (float*)vt;
    proj_gemm<<<dim3(8, 32, 3), 256, PSMB>>>(p1);

    fmha<<<512, 256, FSMB>>>(mask, attn);

    PP3 p2;
    for (int z = 0; z < 3; ++z) {
        p2.Ah[z] = (const unsigned*)oph;
        p2.Al[z] = (const unsigned*)opl;
        p2.Bh[z] = (const unsigned*)wth + (size_t)3 * WW;
        p2.Bl[z] = (const unsigned*)wtl + (size_t)3 * WW;
        p2.bias[z] = bo;
        p2.scale[z] = 1.0f;
        p2.mode[z] = 0;
        p2.outF[z] = out;
        p2.oPh[z] = nullptr;
        p2.oPl[z] = nullptr;
    }
    proj_gemm<<<dim3(8, 32, 1), 256, PSMB>>>(p2);
}